// round 1
// baseline (speedup 1.0000x reference)
#include <cuda_runtime.h>
#include <math.h>

#define B_   4
#define Q_   75
#define C_   640
#define M_   196
#define N_   5
#define KS_  5
#define BQ_  (B_*Q_)      // 300
#define HALF_MS 98
#define KB   8
#define TPB_G 392         // 28 x 14 threads, 7x7 register tile

// ---------------- scratch (static device globals; no runtime allocation) ---
__device__ float g_supn[B_*N_*C_*M_];          // 10 MB  (b,n,c,m) normalized class means
__device__ float g_qn  [B_*Q_*C_*M_];          // 150 MB (b,q,c,m) normalized queries
__device__ float g_rowmax[BQ_*N_*2*M_];        // per (bq,n,half,mq): max over ms
__device__ int   g_rowarg[BQ_*N_*2*M_];        // per (bq,n,half,mq): argmax ms (global ms idx)
__device__ float g_loss[BQ_];

// ---------------- support: k-shot mean + L2 normalize over c ---------------
__global__ void support_prep(const float* __restrict__ sup) {
    int bn = blockIdx.x;            // 0..19  (b*5 + n)
    int tid = threadIdx.x;
    __shared__ float rinv[M_];
    const float* base = sup + (size_t)bn * KS_ * C_ * M_;   // (b*25 + n*5) * C*M
    float* out = g_supn + (size_t)bn * C_ * M_;

    // pass 1: mean over k shots
    for (int idx = tid; idx < C_*M_; idx += blockDim.x) {
        float s = 0.f;
        #pragma unroll
        for (int k = 0; k < KS_; k++) s += base[(size_t)k*C_*M_ + idx];
        out[idx] = s * 0.2f;
    }
    __syncthreads();
    // pass 2: per-m norm over c (deterministic serial per thread, no atomics)
    if (tid < M_) {
        float s = 0.f;
        for (int c = 0; c < C_; c++) { float v = out[c*M_ + tid]; s += v*v; }
        rinv[tid] = 1.0f / fmaxf(sqrtf(s), 1e-8f);
    }
    __syncthreads();
    // pass 3: scale
    for (int idx = tid; idx < C_*M_; idx += blockDim.x)
        out[idx] *= rinv[idx % M_];
}

// ---------------- query: L2 normalize over c --------------------------------
__global__ void query_prep(const float* __restrict__ qf) {
    int bq = blockIdx.x;            // 0..299
    int tid = threadIdx.x;
    __shared__ float rinv[M_];
    const float* base = qf + (size_t)bq * C_ * M_;
    float* out = g_qn + (size_t)bq * C_ * M_;
    if (tid < M_) {
        float s = 0.f;
        for (int c = 0; c < C_; c++) { float v = base[c*M_ + tid]; s += v*v; }
        rinv[tid] = 1.0f / fmaxf(sqrtf(s), 1e-8f);
    }
    __syncthreads();
    for (int idx = tid; idx < C_*M_; idx += blockDim.x)
        out[idx] = base[idx] * rinv[idx % M_];
}

// ---------------- main GEMM + row max/argmax --------------------------------
// One CTA: S_tile[mq=196][ms=98] = sum_c qn[c][mq]*supn[c][ms], then per-mq
// max/argmax over ms (first occurrence on tie).
union GemmSmem {
    struct { float A[KB][M_]; float B[KB][HALF_MS]; } t;   // 9408 B
    struct { float v[M_*14]; int c[M_*14]; } r;            // 21952 B
};

__global__ void __launch_bounds__(TPB_G)
gemm_kernel() {
    int half = blockIdx.x;          // 0/1 : ms range [half*98, half*98+98)
    int n    = blockIdx.y;          // 0..4
    int bq   = blockIdx.z;          // 0..299
    int b    = bq / Q_;

    __shared__ GemmSmem sm;

    int tid = threadIdx.x;
    int tx  = tid % 14;             // ms group
    int ty  = tid / 14;             // mq group (0..27)

    const float* Aptr = g_qn   + (size_t)bq * C_ * M_;
    const float* Bptr = g_supn + (size_t)(b*N_ + n) * C_ * M_ + half * HALF_MS;

    float acc[7][7];
    #pragma unroll
    for (int i = 0; i < 7; i++)
        #pragma unroll
        for (int j = 0; j < 7; j++) acc[i][j] = 0.f;

    for (int kt = 0; kt < C_/KB; kt++) {
        // load A chunk (8 x 196) and B chunk (8 x 98)
        for (int l = tid; l < KB*M_; l += TPB_G) {
            int kk = l / M_, m = l % M_;
            sm.t.A[kk][m] = Aptr[(size_t)(kt*KB + kk)*M_ + m];
        }
        for (int l = tid; l < KB*HALF_MS; l += TPB_G) {
            int kk = l / HALF_MS, m = l % HALF_MS;
            sm.t.B[kk][m] = Bptr[(size_t)(kt*KB + kk)*M_ + m];
        }
        __syncthreads();
        #pragma unroll
        for (int kk = 0; kk < KB; kk++) {
            float a[7], bb[7];
            #pragma unroll
            for (int i = 0; i < 7; i++) a[i]  = sm.t.A[kk][ty*7 + i];
            #pragma unroll
            for (int j = 0; j < 7; j++) bb[j] = sm.t.B[kk][tx*7 + j];
            #pragma unroll
            for (int i = 0; i < 7; i++)
                #pragma unroll
                for (int j = 0; j < 7; j++)
                    acc[i][j] += a[i]*bb[j];
        }
        __syncthreads();
    }

    // per-thread row reduction (7 rows x 7 cols), first-occurrence tie (strict >)
    #pragma unroll
    for (int i = 0; i < 7; i++) {
        float bv = acc[i][0]; int bj = 0;
        #pragma unroll
        for (int j = 1; j < 7; j++)
            if (acc[i][j] > bv) { bv = acc[i][j]; bj = j; }
        sm.r.v[(ty*7 + i)*14 + tx] = bv;
        sm.r.c[(ty*7 + i)*14 + tx] = half*HALF_MS + tx*7 + bj;
    }
    __syncthreads();
    if (tid < M_) {
        float bv = sm.r.v[tid*14 + 0]; int bc = sm.r.c[tid*14 + 0];
        #pragma unroll
        for (int t = 1; t < 14; t++) {            // ascending tx == ascending ms
            float v = sm.r.v[tid*14 + t];
            if (v > bv) { bv = v; bc = sm.r.c[tid*14 + t]; }
        }
        int o = ((bq*N_ + n)*2 + half)*M_ + tid;
        g_rowmax[o] = bv;
        g_rowarg[o] = bc;
    }
}

// ---------------- per-(b,q) mutual-NN mask + predict + loss -----------------
__global__ void combine_kernel(const int* __restrict__ qy) {
    int bq = blockIdx.x;
    int tid = threadIdx.x;          // 256 threads

    __shared__ float rowm[N_][M_];  // max over all ms per (n,mq)
    __shared__ float bestv[M_];     // global max over (n,ms) per mq
    __shared__ int   bestj[M_];     // its flattened index n*M + ms
    __shared__ int   maskf[M_];
    __shared__ float pred[N_];

    if (tid < M_) {
        float bv = -1e30f; int bj = 0;
        #pragma unroll
        for (int nn = 0; nn < N_; nn++) {
            int o0 = ((bq*N_ + nn)*2 + 0)*M_ + tid;
            int o1 = ((bq*N_ + nn)*2 + 1)*M_ + tid;
            float m0 = g_rowmax[o0]; int a0 = g_rowarg[o0];
            float m1 = g_rowmax[o1]; int a1 = g_rowarg[o1];
            float rv; int ra;
            if (m1 > m0) { rv = m1; ra = a1; } else { rv = m0; ra = a0; }
            rowm[nn][tid] = rv;
            if (rv > bv) { bv = rv; bj = nn*M_ + ra; }   // ascending n: first occurrence
        }
        bestv[tid] = bv; bestj[tid] = bj;
    }
    __syncthreads();

    // mutual-NN: mq is masked iff it is the (first) argmax among all mq'
    // choosing the same support index j, and class_wise_max (= bv+1) > 0.
    if (tid < M_) {
        float v = bestv[tid]; int j = bestj[tid];
        int ok = (v + 1.0f) > 0.0f;
        for (int t = 0; t < M_; t++) {
            if (t == tid) continue;
            if (bestj[t] == j) {
                float vt = bestv[t];
                if (vt > v || (vt == v && t < tid)) ok = 0;
            }
        }
        maskf[tid] = ok;
    }
    __syncthreads();

    if (tid < N_) {                 // deterministic fixed-order sum
        float s = 0.f;
        for (int m = 0; m < M_; m++)
            if (maskf[m]) s += rowm[tid][m];
        pred[tid] = 2.0f * s;       // TEMPERATURE
    }
    __syncthreads();

    if (tid == 0) {
        float mx = pred[0];
        #pragma unroll
        for (int nn = 1; nn < N_; nn++) mx = fmaxf(mx, pred[nn]);
        float se = 0.f;
        #pragma unroll
        for (int nn = 0; nn < N_; nn++) se += expf(pred[nn] - mx);
        float lse = mx + logf(se);
        int y = qy[bq];
        g_loss[bq] = lse - pred[y];
    }
}

// ---------------- final deterministic mean ----------------------------------
__global__ void final_kernel(float* __restrict__ out) {
    if (threadIdx.x == 0) {
        float s = 0.f;
        for (int i = 0; i < BQ_; i++) s += g_loss[i];
        out[0] = s / (float)BQ_;
    }
}

extern "C" void kernel_launch(void* const* d_in, const int* in_sizes, int n_in,
                              void* d_out, int out_size) {
    const float* sup = (const float*)d_in[0];
    // d_in[1] = support_y : unused by the reference computation
    const float* qf  = (const float*)d_in[2];
    const int*   qy  = (const int*)d_in[3];

    support_prep<<<B_*N_, 256>>>(sup);
    query_prep  <<<BQ_,   256>>>(qf);

    dim3 grid(2, N_, BQ_);
    gemm_kernel<<<grid, TPB_G>>>();

    combine_kernel<<<BQ_, 256>>>(qy);
    final_kernel  <<<1, 32>>>((float*)d_out);
}

// round 5
// speedup vs baseline: 2.5242x; 2.5242x over previous
#include <cuda_runtime.h>
#include <cuda_bf16.h>
#include <math.h>
#include <stdint.h>

#define B_   4
#define Q_   75
#define C_   640
#define M_   196
#define N_   5
#define KS_  5
#define BQ_  (B_*Q_)        // 300
#define MT_  115            // M tiles of 128 per batch (115*128 = 14720)
#define RPB  14720          // padded query rows per batch
#define NPAD 224            // padded ms per class
#define KC   32             // K chunk (bf16)
#define KT_  (C_/KC)        // 20

// smem stage layout (bytes), row stride 80B (40 bf16) => conflict-free ldmatrix
#define ROWB   80
#define AHI_O  0
#define ALO_O  10240
#define BHI_O  20480
#define BLO_O  29440
#define STAGEB 38400
#define SMEM_BYTES (2*STAGEB)

// ---------------- scratch (static device globals; zero-initialized) --------
__device__ __nv_bfloat16 g_qn_hi[(size_t)B_*RPB*C_];   // pad rows stay 0
__device__ __nv_bfloat16 g_qn_lo[(size_t)B_*RPB*C_];
__device__ __nv_bfloat16 g_sn_hi[B_*N_*NPAD*C_];       // pad rows 196..223 stay 0
__device__ __nv_bfloat16 g_sn_lo[B_*N_*NPAD*C_];
__device__ float g_supmean[B_*N_*C_*M_];
__device__ float g_rowmax[BQ_*N_*2*M_];
__device__ int   g_rowarg[BQ_*N_*2*M_];
__device__ float g_loss[BQ_];

// ---------------- PTX helpers ----------------------------------------------
__device__ __forceinline__ uint32_t s2u(const void* p) {
    uint32_t a;
    asm("{ .reg .u64 t; cvta.to.shared.u64 t, %1; cvt.u32.u64 %0, t; }"
        : "=r"(a) : "l"(p));
    return a;
}
__device__ __forceinline__ void cp16(uint32_t dst, const void* src) {
    asm volatile("cp.async.cg.shared.global [%0], [%1], 16;" :: "r"(dst), "l"(src));
}
__device__ __forceinline__ void ldsm4(uint32_t* r, uint32_t a) {
    asm volatile("ldmatrix.sync.aligned.m8n8.x4.shared.b16 {%0,%1,%2,%3}, [%4];"
                 : "=r"(r[0]), "=r"(r[1]), "=r"(r[2]), "=r"(r[3]) : "r"(a));
}
__device__ __forceinline__ void ldsm2(uint32_t* r, uint32_t a) {
    asm volatile("ldmatrix.sync.aligned.m8n8.x2.shared.b16 {%0,%1}, [%2];"
                 : "=r"(r[0]), "=r"(r[1]) : "r"(a));
}
__device__ __forceinline__ void mma16816(float* c, const uint32_t* a, const uint32_t* b) {
    asm volatile("mma.sync.aligned.m16n8k16.row.col.f32.bf16.bf16.f32 "
                 "{%0,%1,%2,%3}, {%4,%5,%6,%7}, {%8,%9}, {%0,%1,%2,%3};"
                 : "+f"(c[0]), "+f"(c[1]), "+f"(c[2]), "+f"(c[3])
                 : "r"(a[0]), "r"(a[1]), "r"(a[2]), "r"(a[3]), "r"(b[0]), "r"(b[1]));
}

// ---------------- support: k-shot mean + L2 norm + transpose to bf16 hi/lo --
__global__ void support_prep_t(const float* __restrict__ sup) {
    int bn = blockIdx.x;                 // b*5 + n
    int tid = threadIdx.x;
    __shared__ float rinv[M_];
    __shared__ float tile[32][33];
    const float* base = sup + (size_t)bn * KS_ * C_ * M_;
    float* mean = g_supmean + (size_t)bn * C_ * M_;

    for (int idx = tid; idx < C_*M_; idx += 256) {
        float s = 0.f;
        #pragma unroll
        for (int k = 0; k < KS_; k++) s += base[(size_t)k*C_*M_ + idx];
        mean[idx] = s * 0.2f;
    }
    __syncthreads();
    if (tid < M_) {
        float s = 0.f;
        for (int c = 0; c < C_; c++) { float v = mean[(size_t)c*M_ + tid]; s += v*v; }
        rinv[tid] = 1.0f / fmaxf(sqrtf(s), 1e-8f);
    }
    __syncthreads();

    int x = tid & 31, y = tid >> 5;
    size_t ob = (size_t)bn * NPAD * C_;
    for (int tc = 0; tc < C_/32; tc++) {
        for (int tm = 0; tm < 7; tm++) {
            int m0 = tm * 32;
            for (int yy = y; yy < 32; yy += 8) {
                int m = m0 + x;
                float v = (m < M_) ? mean[(size_t)(tc*32 + yy)*M_ + m] * rinv[m] : 0.f;
                tile[yy][x] = v;
            }
            __syncthreads();
            for (int yy = y; yy < 32; yy += 8) {
                int m = m0 + yy;
                if (m < M_) {
                    float v = tile[x][yy];
                    __nv_bfloat16 h = __float2bfloat16(v);
                    size_t o = ob + (size_t)m*C_ + tc*32 + x;
                    g_sn_hi[o] = h;
                    g_sn_lo[o] = __float2bfloat16(v - __bfloat162float(h));
                }
            }
            __syncthreads();
        }
    }
}

// ---------------- query: L2 norm + transpose to bf16 hi/lo ------------------
__global__ void query_prep_t(const float* __restrict__ qf) {
    int bq = blockIdx.x;
    int b = bq / Q_, q = bq % Q_;
    int tid = threadIdx.x;
    __shared__ float rinv[M_];
    __shared__ float tile[32][33];
    const float* in = qf + (size_t)bq * C_ * M_;
    size_t rowbase = (size_t)b * RPB + (size_t)q * M_;

    if (tid < M_) {
        float s = 0.f;
        for (int c = 0; c < C_; c++) { float v = in[(size_t)c*M_ + tid]; s += v*v; }
        rinv[tid] = 1.0f / fmaxf(sqrtf(s), 1e-8f);
    }
    __syncthreads();

    int x = tid & 31, y = tid >> 5;
    for (int tc = 0; tc < C_/32; tc++) {
        for (int tm = 0; tm < 7; tm++) {
            int m0 = tm * 32;
            for (int yy = y; yy < 32; yy += 8) {
                int m = m0 + x;
                float v = (m < M_) ? in[(size_t)(tc*32 + yy)*M_ + m] * rinv[m] : 0.f;
                tile[yy][x] = v;
            }
            __syncthreads();
            for (int yy = y; yy < 32; yy += 8) {
                int m = m0 + yy;
                if (m < M_) {
                    float v = tile[x][yy];
                    __nv_bfloat16 h = __float2bfloat16(v);
                    size_t o = (rowbase + m)*C_ + tc*32 + x;
                    g_qn_hi[o] = h;
                    g_qn_lo[o] = __float2bfloat16(v - __bfloat162float(h));
                }
            }
            __syncthreads();
        }
    }
}

// ---------------- HMMA GEMM (split-bf16 x3) + row max/argmax epilogue -------
// CTA: tile 128(mq) x 112(ms) for one (b, mtile, class, half). 8 warps 4x2,
// warp tile 32x56. Double-buffered cp.async, K chunks of 32.
// Row reduction: per-warp partial (56 cols) -> smem merge across wc=0/1 ->
// single deterministic store per row.
__global__ void __launch_bounds__(256)
gemm_hmma() {
    int nh = blockIdx.x;             // n*2 + half  (fastest: A-tile L2 reuse)
    int n = nh >> 1, half = nh & 1;
    int mt = blockIdx.y, b = blockIdx.z;

    extern __shared__ char dynsm[];
    uint32_t sbase = s2u(dynsm);

    int tid = threadIdx.x, lane = tid & 31, wid = tid >> 5;
    int wr = wid >> 1, wc = wid & 1;

    const size_t arbase = (size_t)b * RPB + (size_t)mt * 128;
    const size_t brbase = (size_t)(b*N_ + n) * NPAD + (size_t)half * 112;

    float acc[2][7][4];
    #pragma unroll
    for (int i = 0; i < 2; i++)
        #pragma unroll
        for (int j = 0; j < 7; j++)
            #pragma unroll
            for (int p = 0; p < 4; p++) acc[i][j][p] = 0.f;

    // ---- async tile loader ----
    auto issue = [&](int stage, int kt) {
        uint32_t so = sbase + stage * STAGEB;
        for (int i = tid; i < 512; i += 256) {        // A: 128 rows x 4 chunks
            int r = i >> 2, c = i & 3;
            size_t go = (arbase + r) * C_ + kt*KC + c*8;
            uint32_t ds = so + r*ROWB + c*16;
            cp16(ds + AHI_O, g_qn_hi + go);
            cp16(ds + ALO_O, g_qn_lo + go);
        }
        for (int i = tid; i < 448; i += 256) {        // B: 112 rows x 4 chunks
            int r = i >> 2, c = i & 3;
            size_t go = (brbase + r) * C_ + kt*KC + c*8;
            uint32_t ds = so + BHI_O + r*ROWB + c*16;
            cp16(ds, g_sn_hi + go);
            cp16(ds + (BLO_O - BHI_O), g_sn_lo + go);
        }
        asm volatile("cp.async.commit_group;" ::: "memory");
    };

    issue(0, 0);

    #pragma unroll 1
    for (int kt = 0; kt < KT_; kt++) {
        if (kt + 1 < KT_) {
            issue((kt + 1) & 1, kt + 1);
            asm volatile("cp.async.wait_group 1;" ::: "memory");
        } else {
            asm volatile("cp.async.wait_group 0;" ::: "memory");
        }
        __syncthreads();

        uint32_t so = sbase + (kt & 1) * STAGEB;

        uint32_t Ahi[2][2][4], Alo[2][2][4];
        #pragma unroll
        for (int i = 0; i < 2; i++)
            #pragma unroll
            for (int ks = 0; ks < 2; ks++) {
                int row = wr*32 + i*16 + (lane & 7) + ((lane >> 3) & 1) * 8;
                int col = ks*16 + ((lane >> 4) & 1) * 8;
                uint32_t ad = so + row*ROWB + col*2;
                ldsm4(Ahi[i][ks], ad + AHI_O);
                ldsm4(Alo[i][ks], ad + ALO_O);
            }

        #pragma unroll
        for (int j = 0; j < 7; j++) {
            uint32_t Bhi[2][2], Blo[2][2];
            #pragma unroll
            for (int ks = 0; ks < 2; ks++) {
                int row = wc*56 + j*8 + (lane & 7);
                int col = ks*16 + ((lane >> 3) & 1) * 8;
                uint32_t bd = so + BHI_O + row*ROWB + col*2;
                ldsm2(Bhi[ks], bd);
                ldsm2(Blo[ks], bd + (BLO_O - BHI_O));
            }
            #pragma unroll
            for (int ks = 0; ks < 2; ks++)
                #pragma unroll
                for (int i = 0; i < 2; i++) {
                    mma16816(acc[i][j], Ahi[i][ks], Bhi[ks]);
                    mma16816(acc[i][j], Ahi[i][ks], Blo[ks]);
                    mma16816(acc[i][j], Alo[i][ks], Bhi[ks]);
                }
        }
        __syncthreads();
    }

    // ---- epilogue: per-row max/argmax (first-occurrence ties) ----
    // Stage 1: per-warp partial over its 56 columns -> smem planes per wc.
    float* sv = (float*)dynsm;            // [2][128]
    int*   sc = (int*)(dynsm + 1024);     // [2][128]

    int rq = lane >> 2, cq = lane & 3;
    #pragma unroll
    for (int i = 0; i < 2; i++) {
        #pragma unroll
        for (int rh = 0; rh < 2; rh++) {
            float bv = -1e30f; int bc = 0x7fffffff;
            #pragma unroll
            for (int j = 0; j < 7; j++) {
                #pragma unroll
                for (int p = 0; p < 2; p++) {
                    int gc = half*112 + wc*56 + j*8 + cq*2 + p;
                    float v = acc[i][j][rh*2 + p];
                    if (gc < M_ && (v > bv || (v == bv && gc < bc))) { bv = v; bc = gc; }
                }
            }
            #pragma unroll
            for (int off = 1; off < 4; off <<= 1) {
                float ov = __shfl_xor_sync(0xffffffffu, bv, off);
                int   oc = __shfl_xor_sync(0xffffffffu, bc, off);
                if (ov > bv || (ov == bv && oc < bc)) { bv = ov; bc = oc; }
            }
            if (cq == 0) {
                int rl = wr*32 + i*16 + rh*8 + rq;      // CTA-local row 0..127
                sv[wc*128 + rl] = bv;
                sc[wc*128 + rl] = bc;
            }
        }
    }
    __syncthreads();

    // Stage 2: merge wc halves; lower-ms half (wc=0) wins ties. Single writer.
    if (tid < 128) {
        float v0 = sv[tid],       v1 = sv[128 + tid];
        int   c0 = sc[tid],       c1 = sc[128 + tid];
        float bv; int bc;
        if (v1 > v0) { bv = v1; bc = c1; } else { bv = v0; bc = c0; }
        int gr = mt*128 + tid;
        if (gr < Q_*M_) {
            int q = gr / M_, mq = gr % M_;
            int o = (((b*Q_ + q)*N_ + n)*2 + half)*M_ + mq;
            g_rowmax[o] = bv;
            g_rowarg[o] = bc;
        }
    }
}

// ---------------- per-(b,q) mutual-NN mask + predict + loss -----------------
__global__ void combine_kernel(const int* __restrict__ qy) {
    int bq = blockIdx.x;
    int tid = threadIdx.x;          // 256 threads

    __shared__ float rowm[N_][M_];
    __shared__ float bestv[M_];
    __shared__ int   bestj[M_];
    __shared__ int   maskf[M_];
    __shared__ float pred[N_];

    if (tid < M_) {
        float bv = -1e30f; int bj = 0;
        #pragma unroll
        for (int nn = 0; nn < N_; nn++) {
            int o0 = ((bq*N_ + nn)*2 + 0)*M_ + tid;
            int o1 = ((bq*N_ + nn)*2 + 1)*M_ + tid;
            float m0 = g_rowmax[o0]; int a0 = g_rowarg[o0];
            float m1 = g_rowmax[o1]; int a1 = g_rowarg[o1];
            float rv; int ra;
            if (m1 > m0) { rv = m1; ra = a1; } else { rv = m0; ra = a0; }
            rowm[nn][tid] = rv;
            if (rv > bv) { bv = rv; bj = nn*M_ + ra; }   // ascending n: first occurrence
        }
        bestv[tid] = bv; bestj[tid] = bj;
    }
    __syncthreads();

    if (tid < M_) {
        float v = bestv[tid]; int j = bestj[tid];
        int ok = (v + 1.0f) > 0.0f;
        for (int t = 0; t < M_; t++) {
            if (t == tid) continue;
            if (bestj[t] == j) {
                float vt = bestv[t];
                if (vt > v || (vt == v && t < tid)) ok = 0;
            }
        }
        maskf[tid] = ok;
    }
    __syncthreads();

    if (tid < N_) {                 // deterministic fixed-order sum
        float s = 0.f;
        for (int m = 0; m < M_; m++)
            if (maskf[m]) s += rowm[tid][m];
        pred[tid] = 2.0f * s;       // TEMPERATURE
    }
    __syncthreads();

    if (tid == 0) {
        float mx = pred[0];
        #pragma unroll
        for (int nn = 1; nn < N_; nn++) mx = fmaxf(mx, pred[nn]);
        float se = 0.f;
        #pragma unroll
        for (int nn = 0; nn < N_; nn++) se += expf(pred[nn] - mx);
        float lse = mx + logf(se);
        int y = qy[bq];
        g_loss[bq] = lse - pred[y];
    }
}

__global__ void final_kernel(float* __restrict__ out) {
    if (threadIdx.x == 0) {
        float s = 0.f;
        for (int i = 0; i < BQ_; i++) s += g_loss[i];
        out[0] = s / (float)BQ_;
    }
}

extern "C" void kernel_launch(void* const* d_in, const int* in_sizes, int n_in,
                              void* d_out, int out_size) {
    const float* sup = (const float*)d_in[0];
    // d_in[1] = support_y : unused by the reference computation
    const float* qf  = (const float*)d_in[2];
    const int*   qy  = (const int*)d_in[3];

    cudaFuncSetAttribute(gemm_hmma, cudaFuncAttributeMaxDynamicSharedMemorySize, SMEM_BYTES);

    support_prep_t<<<B_*N_, 256>>>(sup);
    query_prep_t  <<<BQ_,   256>>>(qf);

    dim3 grid(N_*2, MT_, B_);   // nh fastest -> adjacent CTAs share A tile in L2
    gemm_hmma<<<grid, 256, SMEM_BYTES>>>();

    combine_kernel<<<BQ_, 256>>>(qy);
    final_kernel  <<<1, 32>>>((float*)d_out);
}